// round 17
// baseline (speedup 1.0000x reference)
#include <cuda_runtime.h>
#include <cstdint>
#include <cstddef>

#define S_LEN 4096
#define D_DIM 2048
#define V_DIM 64000
#define NBINS (1 << 20)     // bin = key >> 12
#define BIN_SMEM 2048
#define NSEG 16             // split-K segments for the big GEMV
#define NBLK 128            // persistent blocks (<= SM count: residency guaranteed)
#define NTHR 256
#define GSZ (NBLK * NTHR)   // 32768 threads

// ---------------- static scratch (no allocations allowed) ----------------
__device__ float  g_s[S_LEN];
__device__ float  g_scores[S_LEN];
__device__ double g_poolacc[D_DIM];
__device__ double g_logit_part[NSEG][V_DIM];
__device__ float  g_logits[V_DIM];
__device__ unsigned g_maxi;        // monotone-encoded max logit
__device__ unsigned g_smaxi;       // monotone-encoded max score-logit
__device__ double g_zs;            // score softmax denominator (fp64 atomic)
__device__ double g_zacc;          // prob softmax denominator (fp64 atomic)
__device__ float  g_e[V_DIM];
__device__ unsigned g_key[V_DIM];
__device__ unsigned g_hist[NBINS];
__device__ unsigned g_base[NBINS];     // within-block-slice suffix-exclusive
__device__ unsigned g_fill[NBINS];
__device__ unsigned g_blocksum[NBLK];
__device__ unsigned g_blockbase[NBLK]; // cross-slice suffix-exclusive
__device__ int      g_nbins;
__device__ int      g_binlist[NBINS];
__device__ unsigned g_slotkey[V_DIM];
__device__ int      g_slotidx[V_DIM];
__device__ float    g_sortp[V_DIM];
__device__ int      g_order[V_DIM];
__device__ unsigned char g_mask[V_DIM];
__device__ unsigned long long g_best;
__device__ unsigned g_bar_cnt = 0;
__device__ unsigned g_bar_gen = 0;

// ---------------- device grid barrier (all blocks resident) ----------------
__device__ __forceinline__ void gridsync() {
    __syncthreads();
    __threadfence();
    if (threadIdx.x == 0) {
        unsigned gen = atomicAdd(&g_bar_gen, 0u);
        if (atomicAdd(&g_bar_cnt, 1u) == gridDim.x - 1) {
            g_bar_cnt = 0;            // safe: all blocks have arrived
            __threadfence();
            atomicAdd(&g_bar_gen, 1u);
        } else {
            while (atomicAdd(&g_bar_gen, 0u) == gen) {}
        }
    }
    __syncthreads();
}

__device__ __forceinline__ unsigned enc_f(float f) {
    unsigned u = __float_as_uint(f);
    return (u & 0x80000000u) ? ~u : (u | 0x80000000u);
}
__device__ __forceinline__ float dec_f(unsigned e) {
    return (e & 0x80000000u) ? __uint_as_float(e & 0x7FFFFFFFu)
                             : __uint_as_float(~e);
}

// ---------------- threefry2x32 (bit-exact JAX PRNG) ----------------
__device__ __forceinline__ uint32_t rotl32(uint32_t v, int n) {
    return (v << n) | (v >> (32 - n));
}

__device__ __forceinline__ void threefry2x32(uint32_t k0, uint32_t k1,
                                             uint32_t& x0, uint32_t& x1) {
    uint32_t ks[3] = {k0, k1, k0 ^ k1 ^ 0x1BD11BDAu};
    const int rotA[4] = {13, 15, 26, 6};
    const int rotB[4] = {17, 29, 16, 24};
    x0 += ks[0]; x1 += ks[1];
#pragma unroll
    for (int i = 0; i < 5; i++) {
        const int* r = (i & 1) ? rotB : rotA;
#pragma unroll
        for (int k = 0; k < 4; k++) {
            x0 += x1;
            x1 = rotl32(x1, r[k]);
            x1 ^= x0;
        }
        x0 += ks[(i + 1) % 3];
        x1 += ks[(i + 2) % 3] + (uint32_t)(i + 1);
    }
}

// ================= kernel 1: prep (clears + scores + softmax + pool) =========
__global__ void __launch_bounds__(NTHR) k_prep(const float* __restrict__ batch,
                                               const float* __restrict__ pw) {
    int t = threadIdx.x, b = blockIdx.x;
    int gtid = b * NTHR + t;
    __shared__ double sd[NTHR];
    __shared__ unsigned su[NTHR];

    // phase 0: clear per-replay state
    for (int i = gtid; i < D_DIM; i += GSZ) g_poolacc[i] = 0.0;
    if (gtid == 0) {
        g_best = 0ull; g_nbins = 0; g_maxi = 0u; g_smaxi = 0u;
        g_zs = 0.0; g_zacc = 0.0;
    }
    gridsync();

    // phase 1: s[j] = batch[j,:] . pool_w  (warp per row; fp64 4-chain fold)
    int gw = gtid >> 5, lane = gtid & 31;
    const float4* pw4 = reinterpret_cast<const float4*>(pw);
    for (int j = gw; j < S_LEN; j += (GSZ >> 5)) {
        const float4* row4 = reinterpret_cast<const float4*>(batch + (size_t)j * D_DIM);
        double ax = 0.0, ay = 0.0, az = 0.0, aw = 0.0;
#pragma unroll
        for (int k = 0; k < 16; k++) {
            float4 a = row4[lane + k * 32];
            float4 p = pw4[lane + k * 32];
            ax += (double)(a.x * p.x);
            ay += (double)(a.y * p.y);
            az += (double)(a.z * p.z);
            aw += (double)(a.w * p.w);
        }
        double acc = (ax + ay) + (az + aw);
        for (int o = 16; o > 0; o >>= 1)
            acc += __shfl_down_sync(0xffffffffu, acc, o);
        if (lane == 0) g_s[j] = (float)acc;
    }
    gridsync();

    // phase 2a: exact max of s (monotone-encoded atomicMax)
    unsigned em = 0u;
    for (int i = gtid; i < S_LEN; i += GSZ) em = max(em, enc_f(__ldcg(&g_s[i])));
    su[t] = em;
    __syncthreads();
    for (int o = 128; o > 0; o >>= 1) {
        if (t < o) su[t] = max(su[t], su[t + o]);
        __syncthreads();
    }
    if (t == 0) atomicMax(&g_smaxi, su[0]);
    gridsync();

    // phase 2b: exp + fp64 Z fold
    float gm = dec_f(atomicAdd(&g_smaxi, 0u));
    double loc = 0.0;
    for (int i = gtid; i < S_LEN; i += GSZ) {
        float e = expf(__ldcg(&g_s[i]) - gm);
        g_scores[i] = e;
        loc += (double)e;
    }
    sd[t] = loc;
    __syncthreads();
    for (int o = 128; o > 0; o >>= 1) {
        if (t < o) sd[t] += sd[t + o];
        __syncthreads();
    }
    if (t == 0 && sd[0] != 0.0) atomicAdd(&g_zs, sd[0]);
    gridsync();

    // phase 2c: normalize (fp32 division, matches prior passing kernel)
    float Zs = (float)atomicAdd(&g_zs, 0.0);
    for (int i = gtid; i < S_LEN; i += GSZ) g_scores[i] = g_scores[i] / Zs;
    gridsync();

    // phase 3: pool — block b = j-chunk c (identical per-(c,d) math to R15)
    int j0 = b * 32;
    const float4* b4 = reinterpret_cast<const float4*>(batch);
    for (int d4 = t; d4 < 512; d4 += NTHR) {
        double a0 = 0.0, a1 = 0.0, a2 = 0.0, a3 = 0.0;
#pragma unroll
        for (int jj = 0; jj < 32; jj += 8) {
            float c0 = 0.f, c1 = 0.f, c2 = 0.f, c3 = 0.f;
#pragma unroll
            for (int k = 0; k < 8; k++) {
                int j = j0 + jj + k;
                float s = __ldcg(&g_scores[j]);
                float4 bb = b4[(size_t)j * (D_DIM / 4) + d4];
                c0 = fmaf(s, bb.x, c0);
                c1 = fmaf(s, bb.y, c1);
                c2 = fmaf(s, bb.z, c2);
                c3 = fmaf(s, bb.w, c3);
            }
            a0 += (double)c0; a1 += (double)c1;
            a2 += (double)c2; a3 += (double)c3;
        }
        int d = d4 * 4;
        atomicAdd(&g_poolacc[d + 0], a0);
        atomicAdd(&g_poolacc[d + 1], a1);
        atomicAdd(&g_poolacc[d + 2], a2);
        atomicAdd(&g_poolacc[d + 3], a3);
    }
}

// ========== kernel 2: big GEMV (UNCHANGED from R15 — measured 80% of HBM) ====
__global__ void __launch_bounds__(128) k_logits_part(const float* __restrict__ W) {
    int v4 = blockIdx.x * 128 + threadIdx.x;  // grid.x = 125 -> 16000 float4 lanes
    int seg = blockIdx.y;                      // 0..15
    int d0 = seg * 128;
    __shared__ float sp[128];
    if (threadIdx.x < 128) sp[threadIdx.x] = (float)g_poolacc[d0 + threadIdx.x];
    __syncthreads();
    const float4* wp = reinterpret_cast<const float4*>(W) + (size_t)d0 * (V_DIM / 4) + v4;
    double ax = 0.0, ay = 0.0, az = 0.0, aw = 0.0;
    for (int d = 0; d < 128; d += 16) {
        float4 w[16];
#pragma unroll
        for (int k = 0; k < 16; k++)
            w[k] = wp[(size_t)(d + k) * (V_DIM / 4)];
        float x0 = 0.f, x1 = 0.f, x2 = 0.f, x3 = 0.f;
        float y0 = 0.f, y1 = 0.f, y2 = 0.f, y3 = 0.f;
        float z0 = 0.f, z1 = 0.f, z2 = 0.f, z3 = 0.f;
        float u0 = 0.f, u1 = 0.f, u2 = 0.f, u3 = 0.f;
#pragma unroll
        for (int k = 0; k < 16; k += 4) {
            float p0 = sp[d + k + 0], p1 = sp[d + k + 1];
            float p2 = sp[d + k + 2], p3 = sp[d + k + 3];
            x0 = fmaf(p0, w[k + 0].x, x0); x1 = fmaf(p1, w[k + 1].x, x1);
            x2 = fmaf(p2, w[k + 2].x, x2); x3 = fmaf(p3, w[k + 3].x, x3);
            y0 = fmaf(p0, w[k + 0].y, y0); y1 = fmaf(p1, w[k + 1].y, y1);
            y2 = fmaf(p2, w[k + 2].y, y2); y3 = fmaf(p3, w[k + 3].y, y3);
            z0 = fmaf(p0, w[k + 0].z, z0); z1 = fmaf(p1, w[k + 1].z, z1);
            z2 = fmaf(p2, w[k + 2].z, z2); z3 = fmaf(p3, w[k + 3].z, z3);
            u0 = fmaf(p0, w[k + 0].w, u0); u1 = fmaf(p1, w[k + 1].w, u1);
            u2 = fmaf(p2, w[k + 2].w, u2); u3 = fmaf(p3, w[k + 3].w, u3);
        }
        ax += (double)((x0 + x1) + (x2 + x3));
        ay += (double)((y0 + y1) + (y2 + y3));
        az += (double)((z0 + z1) + (z2 + z3));
        aw += (double)((u0 + u1) + (u2 + u3));
    }
    int v = v4 * 4;
    g_logit_part[seg][v + 0] = ax;
    g_logit_part[seg][v + 1] = ay;
    g_logit_part[seg][v + 2] = az;
    g_logit_part[seg][v + 3] = aw;
}

// ================= kernel 3: fused sampling tail =============================
__global__ void __launch_bounds__(NTHR) k_tail(const float* __restrict__ bias,
                                               float* __restrict__ out) {
    int t = threadIdx.x, b = blockIdx.x;
    int gtid = b * NTHR + t;
    __shared__ unsigned su[NTHR];
    __shared__ double sd[NTHR];
    __shared__ unsigned sk[BIN_SMEM];
    __shared__ int si[BIN_SMEM];

    // phase A: clear hist/fill; logits_final + global max fold
    for (int i = gtid; i < NBINS; i += GSZ) { g_hist[i] = 0u; g_fill[i] = 0u; }
    unsigned em = 0u;
    for (int v = gtid; v < V_DIM; v += GSZ) {
        double s = 0.0;
#pragma unroll
        for (int k = 0; k < NSEG; k++) s += g_logit_part[k][v];
        float m = (float)s;
        m = m + bias[v];
        float lg = 0.7f * m;  // TEMPERATURE
        g_logits[v] = lg;
        em = max(em, enc_f(lg));
    }
    su[t] = em;
    __syncthreads();
    for (int o = 128; o > 0; o >>= 1) {
        if (t < o) su[t] = max(su[t], su[t + o]);
        __syncthreads();
    }
    if (t == 0) atomicMax(&g_maxi, su[0]);
    gridsync();

    // phase B: exp + fp64 Z fold
    float maxl = dec_f(atomicAdd(&g_maxi, 0u));
    double loc = 0.0;
    for (int v = gtid; v < V_DIM; v += GSZ) {
        float e = expf(g_logits[v] - maxl);
        g_e[v] = e;
        loc += (double)e;
    }
    sd[t] = loc;
    __syncthreads();
    for (int o = 128; o > 0; o >>= 1) {
        if (t < o) sd[t] += sd[t + o];
        __syncthreads();
    }
    if (t == 0 && sd[0] != 0.0) atomicAdd(&g_zacc, sd[0]);
    gridsync();

    // phase C: p = e/Z (fp32 division), keys + histogram
    float Z = (float)atomicAdd(&g_zacc, 0.0);
    for (int v = gtid; v < V_DIM; v += GSZ) {
        float p = g_e[v] / Z;
        unsigned key = __float_as_uint(p);
        g_key[v] = key;
        atomicAdd(&g_hist[key >> 12], 1u);
    }
    gridsync();

    // phase D: per-block-slice suffix-exclusive scan (8192 bins/block) + binlist
    {
        int base0 = b * 8192 + t * 32;
        unsigned h[32];
        unsigned tot = 0u;
#pragma unroll
        for (int k = 0; k < 32; k++) { h[k] = __ldcg(&g_hist[base0 + k]); tot += h[k]; }
        su[t] = tot;
        __syncthreads();
        for (int off = 1; off < NTHR; off <<= 1) {
            unsigned add = (t >= off) ? su[t - off] : 0u;
            __syncthreads();
            su[t] += add;
            __syncthreads();
        }
        unsigned total = su[NTHR - 1];
        unsigned running = total - su[t];  // count in this slice strictly above thread t
        for (int k = 31; k >= 0; k--) {
            int bb = base0 + k;
            g_base[bb] = running;
            running += h[k];
            if (h[k]) {
                int p = atomicAdd(&g_nbins, 1);
                g_binlist[p] = bb;
            }
        }
        if (t == 0) g_blocksum[b] = total;
    }
    gridsync();

    // phase E: block 0 suffix-exclusive scan over 128 slice sums
    if (b == 0) {
        unsigned v = (t < NBLK) ? __ldcg(&g_blocksum[t]) : 0u;
        su[t] = v;
        __syncthreads();
        for (int off = 1; off < NTHR; off <<= 1) {
            unsigned add = (t >= off) ? su[t - off] : 0u;
            __syncthreads();
            su[t] += add;
            __syncthreads();
        }
        unsigned total = su[NTHR - 1];
        if (t < NBLK) g_blockbase[t] = total - su[t];
    }
    gridsync();

    // phase F: scatter
    for (int v = gtid; v < V_DIM; v += GSZ) {
        unsigned key = g_key[v];
        unsigned bb = key >> 12;
        unsigned pos = __ldcg(&g_blockbase[bb >> 13]) + __ldcg(&g_base[bb]) +
                       atomicAdd(&g_fill[bb], 1u);
        g_slotkey[pos] = key;
        g_slotidx[pos] = v;
    }
    gridsync();

    // phase G: exact rank within bin (descending key, ties ascending index)
    {
        int nb = atomicAdd(&g_nbins, 0);
        for (int bi = b; bi < nb; bi += NBLK) {
            int bb = __ldcg(&g_binlist[bi]);
            unsigned c = __ldcg(&g_hist[bb]);
            unsigned base = __ldcg(&g_blockbase[bb >> 13]) + __ldcg(&g_base[bb]);
            if (c <= BIN_SMEM) {
                for (unsigned e = t; e < c; e += NTHR) {
                    sk[e] = __ldcg(&g_slotkey[base + e]);
                    si[e] = __ldcg(&g_slotidx[base + e]);
                }
                __syncthreads();
                for (unsigned e = t; e < c; e += NTHR) {
                    unsigned ke = sk[e];
                    int ide = si[e];
                    unsigned r = 0;
                    for (unsigned u = 0; u < c; u++) {
                        unsigned ku = sk[u];
                        r += (ku > ke) || (ku == ke && si[u] < ide);
                    }
                    g_sortp[base + r] = __uint_as_float(ke);
                    g_order[base + r] = ide;
                }
                __syncthreads();
            } else {
                for (unsigned e = t; e < c; e += NTHR) {
                    unsigned ke = __ldcg(&g_slotkey[base + e]);
                    int ide = __ldcg(&g_slotidx[base + e]);
                    unsigned r = 0;
                    for (unsigned u = 0; u < c; u++) {
                        unsigned ku = __ldcg(&g_slotkey[base + u]);
                        r += (ku > ke) || (ku == ke && __ldcg(&g_slotidx[base + u]) < ide);
                    }
                    g_sortp[base + r] = __uint_as_float(ke);
                    g_order[base + r] = ide;
                }
                __syncthreads();
            }
        }
    }
    gridsync();

    // phase H: inclusive fp64 cumsum + top-p mask (block 0; 256 x 250 = 64000)
    if (b == 0) {
        int i0 = t * 250;
        double s = 0.0;
        for (int k = 0; k < 250; k++) s += (double)__ldcg(&g_sortp[i0 + k]);
        sd[t] = s;
        __syncthreads();
        for (int off = 1; off < NTHR; off <<= 1) {
            double add = (t >= off) ? sd[t - off] : 0.0;
            __syncthreads();
            sd[t] += add;
            __syncthreads();
        }
        double run = (t > 0) ? sd[t - 1] : 0.0;
        for (int k = 0; k < 250; k++) {
            int i = i0 + k;
            run += (double)__ldcg(&g_sortp[i]);
            g_mask[i] = (run <= 0.5) ? 1 : 0;
        }
    }
    gridsync();

    // phase I: gumbel-argmax (JAX partitionable threefry, draw = y0 ^ y1)
    for (int i = gtid; i < V_DIM; i += GSZ) {
        if (!g_mask[i]) continue;
        uint32_t x0 = 0u, x1 = (uint32_t)i;
        threefry2x32(0u, 42u, x0, x1);
        uint32_t bits = x0 ^ x1;
        float f = __uint_as_float((bits >> 9) | 0x3f800000u) - 1.0f;  // [0,1)
        float u = (f > 0.0f) ? f : 1.17549435e-38f;                    // minval=tiny
        float g = -logf(-logf(u));
        float val = logf(__ldcg(&g_sortp[i])) + g;
        unsigned ob = enc_f(val);
        unsigned long long pk =
            (((unsigned long long)ob) << 32) |
            (unsigned long long)(0xFFFFFFFFu - (uint32_t)i);  // tie -> smaller i
        atomicMax(&g_best, pk);
    }
    gridsync();

    // phase J: emit token (float32 output)
    if (gtid == 0) {
        unsigned long long bst = atomicAdd(&g_best, 0ull);
        uint32_t i = 0xFFFFFFFFu - (uint32_t)(bst & 0xFFFFFFFFull);
        if (i >= V_DIM) i = 0;
        out[0] = (float)__ldcg(&g_order[i]);
    }
}

// ---------------- launch: 3 kernels, 0 memsets ----------------
extern "C" void kernel_launch(void* const* d_in, const int* in_sizes, int n_in,
                              void* d_out, int out_size) {
    const float* batch = (const float*)d_in[0];
    const float* pw    = (const float*)d_in[1];
    const float* W     = (const float*)d_in[2];
    const float* bias  = (const float*)d_in[3];

    k_prep<<<NBLK, NTHR>>>(batch, pw);
    k_logits_part<<<dim3(125, NSEG), 128>>>(W);
    k_tail<<<NBLK, NTHR>>>(bias, (float*)d_out);
}